// round 4
// baseline (speedup 1.0000x reference)
#include <cuda_runtime.h>
#include <cuda_bf16.h>
#include <cstdint>

// out[t,h] = sum_{g<2} sum_{k<2} buf[g, idx[t,k], h]
// buf: (2, 16384, 4096) fp32 ; idx: (8192, 2) int32 (JAX x64-disabled) ; out: (8192, 4096) fp32
//
// HBM-bound gather+sum: 512 MiB read + 128 MiB write. Vectorized float4,
// 4 independent loads per thread for MLP, full coalescing within each row.

static constexpr int NTOKENS = 8192;
static constexpr int HIDDEN  = 4096;
static constexpr int M_FULL  = 16384;
static constexpr int H4      = HIDDEN / 4;          // 1024 float4 per row
static constexpr long long GSTRIDE4 = (long long)M_FULL * H4;  // float4 stride between groups

__global__ __launch_bounds__(256) void gather_sum_kernel(
    const float4* __restrict__ buf,
    const int* __restrict__ idx,
    float4* __restrict__ out)
{
    const int t  = blockIdx.x;
    const int h4 = blockIdx.y * 256 + threadIdx.x;   // 0..1023

    // Same-address loads across the block -> broadcast, essentially free.
    const int i0 = __ldg(&idx[t * 2 + 0]);
    const int i1 = __ldg(&idx[t * 2 + 1]);

    const long long r0 = (long long)i0 * H4 + h4;
    const long long r1 = (long long)i1 * H4 + h4;

    // 4 independent loads -> MLP=4, hides DRAM latency
    float4 a = __ldg(&buf[r0]);
    float4 b = __ldg(&buf[r1]);
    float4 c = __ldg(&buf[GSTRIDE4 + r0]);
    float4 d = __ldg(&buf[GSTRIDE4 + r1]);

    float4 r;
    r.x = (a.x + b.x) + (c.x + d.x);
    r.y = (a.y + b.y) + (c.y + d.y);
    r.z = (a.z + b.z) + (c.z + d.z);
    r.w = (a.w + b.w) + (c.w + d.w);

    out[(long long)t * H4 + h4] = r;
}

extern "C" void kernel_launch(void* const* d_in, const int* in_sizes, int n_in,
                              void* d_out, int out_size)
{
    const float4* buf = (const float4*)d_in[0];
    const int*    idx = (const int*)d_in[1];
    float4*       out = (float4*)d_out;

    dim3 grid(NTOKENS, H4 / 256);   // 8192 x 4 blocks
    gather_sum_kernel<<<grid, 256>>>(buf, idx, out);
}